// round 15
// baseline (speedup 1.0000x reference)
#include <cuda_runtime.h>
#include <cuda_fp16.h>
#include <math.h>
#include <cstdint>

#define B_  4
#define S_  2048
#define D_  768
#define H_  12
#define DH_ 64
#define M_  (B_*S_)          // 8192
#define NROWS_ (B_*H_*S_)    // 98304
#define QKVN_ (NROWS_*DH_)   // 6291456
#define DD_  (D_*D_)         // 589824
#define LOG2E_ 1.4426950408889634f

// Scratch (allocation-free: static __device__ globals)
__device__ __half g_xf[M_*D_];                     // x fp16
__device__ __half g_wh[3*DD_], g_wl[2*DD_];        // Wq,Wk fp16 split; Wv hi-only
__device__ __half g_wof[DD_];                      // Wo fp16
__device__ __half g_qh[QKVN_];                     // q fp16 (prescaled, normalized)
__device__ __half g_kh[QKVN_];                     // k fp16 (normalized)
__device__ __half g_vh[QKVN_];                     // v fp16
__device__ __half g_cf[M_*D_];                     // ctx fp16

// ===========================================================================
// Helpers
// ===========================================================================
__device__ __forceinline__ uint32_t smem_u32(const void* p) {
    uint32_t r;
    asm("{ .reg .u64 t; cvta.to.shared.u64 t, %1; cvt.u32.u64 %0, t; }"
        : "=r"(r) : "l"(p));
    return r;
}
__device__ __forceinline__ void ldsm_x4(uint32_t* r, uint32_t addr) {
    asm volatile("ldmatrix.sync.aligned.m8n8.x4.shared.b16 {%0,%1,%2,%3}, [%4];"
                 : "=r"(r[0]), "=r"(r[1]), "=r"(r[2]), "=r"(r[3]) : "r"(addr));
}
__device__ __forceinline__ void ldsm_x4_t(uint32_t* r, uint32_t addr) {
    asm volatile("ldmatrix.sync.aligned.m8n8.x4.trans.shared.b16 {%0,%1,%2,%3}, [%4];"
                 : "=r"(r[0]), "=r"(r[1]), "=r"(r[2]), "=r"(r[3]) : "r"(addr));
}
// fp16 in, fp32 accum
__device__ __forceinline__ void mma16816h(float* d, const uint32_t* a,
                                          uint32_t b0, uint32_t b1) {
    asm volatile(
        "mma.sync.aligned.m16n8k16.row.col.f32.f16.f16.f32 "
        "{%0,%1,%2,%3}, {%4,%5,%6,%7}, {%8,%9}, {%0,%1,%2,%3};"
        : "+f"(d[0]), "+f"(d[1]), "+f"(d[2]), "+f"(d[3])
        : "r"(a[0]), "r"(a[1]), "r"(a[2]), "r"(a[3]), "r"(b0), "r"(b1));
}
// fp16 hi/lo split
__device__ __forceinline__ void split2h(float x0, float x1, uint32_t& hi, uint32_t& lo) {
    __half h0 = __float2half_rn(x0);
    __half h1 = __float2half_rn(x1);
    __half l0 = __float2half_rn(x0 - __half2float(h0));
    __half l1 = __float2half_rn(x1 - __half2float(h1));
    hi = (uint32_t)__half_as_ushort(h0) | ((uint32_t)__half_as_ushort(h1) << 16);
    lo = (uint32_t)__half_as_ushort(l0) | ((uint32_t)__half_as_ushort(l1) << 16);
}
// pack two fp32 -> fp16x2 (rn), element0 in low half
__device__ __forceinline__ uint32_t pack2h(float x0, float x1) {
    uint32_t d;
    asm("cvt.rn.f16x2.f32 %0, %1, %2;" : "=r"(d) : "f"(x1), "f"(x0));
    return d;
}
__device__ __forceinline__ float ex2(float x) {
    float y;
    asm("ex2.approx.f32 %0, %1;" : "=f"(y) : "f"(x));
    return y;
}
__device__ __forceinline__ void cp16(uint32_t dst, const void* src) {
    asm volatile("cp.async.cg.shared.global [%0], [%1], 16;" :: "r"(dst), "l"(src));
}
#define CP_COMMIT() asm volatile("cp.async.commit_group;" ::: "memory")
#define CP_WAIT(n)  asm volatile("cp.async.wait_group %0;" :: "n"(n) : "memory")

// ===========================================================================
// conversion kernels
// ===========================================================================
__global__ void __launch_bounds__(256)
xconv_kernel(const float* __restrict__ src)
{
    const int i = (blockIdx.x * 256 + threadIdx.x) * 4;
    float4 v = *reinterpret_cast<const float4*>(src + i);
    *reinterpret_cast<uint2*>(g_xf + i) =
        make_uint2(pack2h(v.x, v.y), pack2h(v.z, v.w));
}
__global__ void __launch_bounds__(256)
wsplit_kernel(const float* __restrict__ Wq, const float* __restrict__ Wk,
              const float* __restrict__ Wv, const float* __restrict__ Wo)
{
    const int per = DD_ / 1024;                   // 576
    const int wsel = blockIdx.x / per;
    const int bx   = blockIdx.x % per;
    const float* src = (wsel == 0) ? Wq : (wsel == 1) ? Wk : (wsel == 2) ? Wv : Wo;
    const int i = (bx * 256 + threadIdx.x) * 4;
    float4 v = *reinterpret_cast<const float4*>(src + i);
    if (wsel < 2) {
        uint32_t h0, l0, h1, l1;
        split2h(v.x, v.y, h0, l0);
        split2h(v.z, v.w, h1, l1);
        const size_t o = (size_t)wsel * DD_ + i;
        *reinterpret_cast<uint2*>(g_wh + o) = make_uint2(h0, h1);
        *reinterpret_cast<uint2*>(g_wl + o) = make_uint2(l0, l1);
    } else if (wsel == 2) {
        *reinterpret_cast<uint2*>(g_wh + 2 * (size_t)DD_ + i) =
            make_uint2(pack2h(v.x, v.y), pack2h(v.z, v.w));
    } else {
        *reinterpret_cast<uint2*>(g_wof + i) =
            make_uint2(pack2h(v.x, v.y), pack2h(v.z, v.w));
    }
}

// ===========================================================================
// fp16 GEMM mainloop: acc = A @ (Wh [+ Wl])^T, 128x128 tile, 3-stage ring.
// use_lo selects 2-combo (q,k) vs 1-combo (v) at uniform runtime cost.
// ===========================================================================
#define LDK_  40
#define GARR  10240
#define GEMM2_SMEM (9 * GARR)       // 3 stages x {A, Wh, Wl} = 90KB

__device__ __forceinline__ void gemm2_body(
    const __half* __restrict__ A,
    const __half* __restrict__ Wh, const __half* __restrict__ Wl,
    int m0, int n0, char* smem, float acc[4][4][4], bool use_lo)
{
    const int tid    = threadIdx.x;
    const int lane   = tid & 31;
    const int wid    = tid >> 5;
    const int warp_m = wid & 1;
    const int warp_n = wid >> 1;
    const uint32_t sb = smem_u32(smem);

#pragma unroll
    for (int i = 0; i < 4; i++)
#pragma unroll
        for (int j = 0; j < 4; j++)
#pragma unroll
            for (int e = 0; e < 4; e++) acc[i][j][e] = 0.f;

    const int grow = tid >> 1;
    const int c16  = (tid & 1) * 2;
    const __half* s0 = A  + (size_t)(m0 + grow) * D_;
    const __half* s1 = Wh + (size_t)(n0 + grow) * D_;
    const __half* s2 = Wl + (size_t)(n0 + grow) * D_;

    auto issue = [&](int kc, int bsel) {
        const uint32_t dst = sb + bsel * 3 * GARR + grow * 80 + c16 * 16;
#pragma unroll
        for (int j = 0; j < 2; j++) {
            cp16(dst + j * 16,        s0 + kc + (c16 + j) * 8);
            cp16(dst + j * 16 + GARR, s1 + kc + (c16 + j) * 8);
            if (use_lo)
                cp16(dst + j * 16 + 2 * GARR, s2 + kc + (c16 + j) * 8);
        }
    };

    const int r_a = lane & 15, c_a = (lane >> 4) * 8;
    const int r_b = (lane & 7) | ((lane >> 4) << 3);
    const int c_b = ((lane >> 3) & 1) * 8;
    const uint32_t offA = ((warp_m * 64 + r_a) * LDK_ + c_a) * 2;
    const uint32_t offB = ((warp_n * 32 + r_b) * LDK_ + c_b) * 2;

    issue(0, 0);  CP_COMMIT();
    issue(32, 1); CP_COMMIT();

    const int NK = D_ / 32;   // 24
    for (int it = 0; it < NK; it++) {
        if (it + 1 < NK) { CP_WAIT(1); } else { CP_WAIT(0); }
        __syncthreads();
        if (it + 2 < NK) { issue((it + 2) * 32, (it + 2) % 3); CP_COMMIT(); }

        const uint32_t bA  = sb + ((it % 3) * 3) * GARR;
        const uint32_t bWh = bA + GARR;
        const uint32_t bWl = bA + 2 * GARR;

#pragma unroll
        for (int ks = 0; ks < 2; ks++) {
            const uint32_t ko = ks * 32;
            uint32_t ah[4][4];
#pragma unroll
            for (int mt = 0; mt < 4; mt++)
                ldsm_x4(ah[mt], bA + offA + ko + mt * 16 * LDK_ * 2);
            uint32_t bh[8], bl[8];
#pragma unroll
            for (int g = 0; g < 2; g++) {
                ldsm_x4(&bh[g * 4], bWh + offB + ko + g * 16 * LDK_ * 2);
                if (use_lo)
                    ldsm_x4(&bl[g * 4], bWl + offB + ko + g * 16 * LDK_ * 2);
            }
#pragma unroll
            for (int mt = 0; mt < 4; mt++)
#pragma unroll
                for (int nt = 0; nt < 4; nt++) {
                    mma16816h(acc[mt][nt], ah[mt], bh[nt * 2], bh[nt * 2 + 1]);
                    if (use_lo)
                        mma16816h(acc[mt][nt], ah[mt], bl[nt * 2], bl[nt * 2 + 1]);
                }
        }
    }
    __syncthreads();
}

// ===========================================================================
// fused QKV GEMM: grid.x = 18 (wsel = x/6: 0=q, 1=k, 2=v).
// q,k: 2-combo + L2 norm (+ scale for q); v: 1-combo + bias only.
// ===========================================================================
__global__ void __launch_bounds__(256, 2)
qkv_gemm(const float* __restrict__ bq, const float* __restrict__ bk,
         const float* __restrict__ bv, const float* __restrict__ ls)
{
    extern __shared__ char smem[];
    const int wsel = blockIdx.x / 6;
    const int n0   = (blockIdx.x % 6) * 128;
    const int m0   = blockIdx.y * 128;

    float acc[4][4][4];
    gemm2_body(g_xf, g_wh + (size_t)wsel * DD_, g_wl + (size_t)(wsel & 1) * DD_,
               m0, n0, smem, acc, wsel < 2);

    const int tid  = threadIdx.x;
    const int lane = tid & 31;
    const int wid  = tid >> 5;
    const int warp_m = wid & 1, warp_n = wid >> 1;

    const float* bias = (wsel == 0) ? bq : (wsel == 1) ? bk : bv;
    __half* dst = (wsel == 0) ? g_qh : (wsel == 1) ? g_kh : g_vh;

    float2 bv2[4];
#pragma unroll
    for (int nt = 0; nt < 4; nt++)
        bv2[nt] = *reinterpret_cast<const float2*>(
            &bias[n0 + warp_n * 32 + nt * 8 + 2 * (lane & 3)]);
#pragma unroll
    for (int mt = 0; mt < 4; mt++)
#pragma unroll
        for (int nt = 0; nt < 4; nt++) {
            acc[mt][nt][0] += bv2[nt].x; acc[mt][nt][1] += bv2[nt].y;
            acc[mt][nt][2] += bv2[nt].x; acc[mt][nt][3] += bv2[nt].y;
        }

    float* sq = reinterpret_cast<float*>(smem);   // [128][4]
    if (wsel < 2) {
#pragma unroll
        for (int mt = 0; mt < 4; mt++)
#pragma unroll
            for (int half = 0; half < 2; half++) {
                const int r = warp_m * 64 + mt * 16 + (lane >> 2) + half * 8;
                float p = 0.f;
#pragma unroll
                for (int nt = 0; nt < 4; nt++) {
                    const float a = acc[mt][nt][half * 2], bvv = acc[mt][nt][half * 2 + 1];
                    p += a * a + bvv * bvv;
                }
                p += __shfl_xor_sync(0xffffffffu, p, 1);
                p += __shfl_xor_sync(0xffffffffu, p, 2);
                if ((lane & 3) == 0) sq[r * 4 + warp_n] = p;
            }
        __syncthreads();
    }

    float scl = 1.f;
    if (wsel == 0) {
        const int hh = 2 * (blockIdx.x % 6) + (warp_n >> 1);
        scl = __expf(fminf(ls[hh], 4.6051701859880914f)) * LOG2E_;
    }

#pragma unroll
    for (int mt = 0; mt < 4; mt++) {
#pragma unroll
        for (int half = 0; half < 2; half++) {
            const int r = warp_m * 64 + mt * 16 + (lane >> 2) + half * 8;
            float inv = 1.f;
            if (wsel < 2) {
                const float s2 = sq[r * 4 + (warp_n & 2)] + sq[r * 4 + (warp_n & 2) + 1];
                inv = scl / fmaxf(sqrtf(s2), 1e-12f);
            }
            const int m  = m0 + r;
            const int bb = m >> 11, ss = m & (S_ - 1);
#pragma unroll
            for (int nt = 0; nt < 4; nt++) {
                const int n  = n0 + warp_n * 32 + nt * 8 + 2 * (lane & 3);
                const int hh = n >> 6, dd = n & 63;
                const size_t idx = (((size_t)(bb * H_ + hh)) * S_ + ss) * DH_ + dd;
                *reinterpret_cast<uint32_t*>(&dst[idx]) =
                    pack2h(acc[mt][nt][half * 2] * inv, acc[mt][nt][half * 2 + 1] * inv);
            }
        }
    }
}

// output projection (1-combo): ctx_f @ Wo^T + bo -> fp32 out
__global__ void __launch_bounds__(256, 2)
o_gemm(const float* __restrict__ bo, float* __restrict__ out)
{
    extern __shared__ char smem[];
    const int n0 = blockIdx.x * 128;
    const int m0 = blockIdx.y * 128;

    float acc[4][4][4];
    gemm2_body(g_cf, g_wof, g_wof, m0, n0, smem, acc, false);

    const int lane = threadIdx.x & 31;
    const int wid  = threadIdx.x >> 5;
    const int warp_m = wid & 1, warp_n = wid >> 1;
#pragma unroll
    for (int mt = 0; mt < 4; mt++) {
#pragma unroll
        for (int nt = 0; nt < 4; nt++) {
            const int n = n0 + warp_n * 32 + nt * 8 + 2 * (lane & 3);
            const float2 bv2 = *reinterpret_cast<const float2*>(&bo[n]);
#pragma unroll
            for (int half = 0; half < 2; half++) {
                const int m = m0 + warp_m * 64 + mt * 16 + (lane >> 2) + half * 8;
                float2 o;
                o.x = acc[mt][nt][half * 2 + 0] + bv2.x;
                o.y = acc[mt][nt][half * 2 + 1] + bv2.y;
                *reinterpret_cast<float2*>(out + (size_t)m * D_ + n) = o;
            }
        }
    }
}

// ===========================================================================
// HMMA flash attention: 128-key tiles, 2-stage double buffer (one sync/iter),
// fixed-max softmax, all single-fp16 tensor path.
// ===========================================================================
#define ABUF2  18432                 // one 128x72 fp16 array
#define ATTN_SMEM (4 * ABUF2)        // 2 stages x {K, V} = 72KB

__global__ void __launch_bounds__(256, 2)
attn_mma(const float* __restrict__ ls)
{
    extern __shared__ char sm[];
    const uint32_t sbase = smem_u32(sm);
    const int tid  = threadIdx.x;
    const int lane = tid & 31;
    const int wid  = tid >> 5;
    const int bh   = blockIdx.y;
    const int h    = bh % H_;
    const int b    = bh / H_;
    const int q0   = blockIdx.x * 128;
    const size_t base = (size_t)bh * S_ * DH_;
    const float Mfix = __expf(fminf(ls[h], 4.6051701859880914f)) * LOG2E_;

    // stage Q (fp16, 128x64) into smem, build A-fragments, release
    {
        const __half* gq = g_qh + base + (size_t)q0 * DH_;
#pragma unroll
        for (int i = 0; i < 4; i++) {
            const int idx = (i << 8) + tid;
            const int row = idx >> 3, c = idx & 7;
            const uint4 v = *reinterpret_cast<const uint4*>(gq + row * DH_ + c * 8);
            *reinterpret_cast<uint4*>(sm + row * 144 + c * 16) = v;
        }
    }
    __syncthreads();
    uint32_t qf[4][4];
    {
        const uint32_t qa = sbase + (wid * 16 + (lane & 15)) * 144 + (lane >> 4) * 16;
#pragma unroll
        for (int kt = 0; kt < 4; kt++)
            ldsm_x4(qf[kt], qa + kt * 32);
    }
    __syncthreads();

    float o[8][4];
#pragma unroll
    for (int nt = 0; nt < 8; nt++)
#pragma unroll
        for (int e = 0; e < 4; e++) o[nt][e] = 0.f;
    float l0 = 0.f, l1 = 0.f;

    const uint32_t lofs = (lane & 15) * 144 + (lane >> 4) * 16;

    const __half* gkh = g_kh + base;
    const __half* gvh = g_vh + base;

    // KV tile = 128 keys: 2 arrays x 128 rows x 8 chunks = 2048, 8/thread
    auto issue = [&](int it, int bsel) {
        const int koff = it * 128 * DH_;
#pragma unroll
        for (int i = 0; i < 8; i++) {
            const int idx = (i << 8) + tid;        // 0..2047
            const int arr = idx >> 10;             // 0..1
            const int row = (idx >> 3) & 127;
            const int c   = idx & 7;
            const __half* gp = (arr == 0 ? gkh : gvh) + koff + row * DH_ + c * 8;
            cp16(sbase + (bsel * 2 + arr) * ABUF2 + row * 144 + c * 16, gp);
        }
    };

    issue(0, 0); CP_COMMIT();

    const int NIT = S_ / 128;   // 16
    for (int it = 0; it < NIT; it++) {
        CP_WAIT(0);
        __syncthreads();
        if (it + 1 < NIT) { issue(it + 1, (it + 1) & 1); CP_COMMIT(); }

        const uint32_t Kh = sbase + ((it & 1) * 2) * ABUF2;
        const uint32_t Vh = Kh + ABUF2;

        auto qk_block = [&](int g, float* s0p, float* s1p) {
#pragma unroll
            for (int e = 0; e < 4; e++) { s0p[e] = -Mfix; s1p[e] = -Mfix; }
#pragma unroll
            for (int kt = 0; kt < 4; kt++) {
                uint32_t kf[4];
                ldsm_x4(kf, Kh + lofs + g * 16 * 144 + kt * 32);
                mma16816h(s0p, qf[kt], kf[0], kf[2]);
                mma16816h(s1p, qf[kt], kf[1], kf[3]);
            }
        };
        auto exppack = [&](float* s0p, float* s1p, uint32_t* ph) {
#pragma unroll
            for (int e = 0; e < 4; e++) { s0p[e] = ex2(s0p[e]); s1p[e] = ex2(s1p[e]); }
            l0 += s0p[0] + s0p[1] + s1p[0] + s1p[1];
            l1 += s0p[2] + s0p[3] + s1p[2] + s1p[3];
            ph[0] = pack2h(s0p[0], s0p[1]);
            ph[1] = pack2h(s0p[2], s0p[3]);
            ph[2] = pack2h(s1p[0], s1p[1]);
            ph[3] = pack2h(s1p[2], s1p[3]);
        };
        auto pv_block = [&](int g, const uint32_t* ph) {
#pragma unroll
            for (int og = 0; og < 4; og++) {
                uint32_t vf[4];
                ldsm_x4_t(vf, Vh + lofs + g * 16 * 144 + og * 32);
                mma16816h(o[2 * og],     ph, vf[0], vf[1]);
                mma16816h(o[2 * og + 1], ph, vf[2], vf[3]);
            }
        };

        // 8 key blocks of 16, software-pipelined (E/O register sets)
        float sE0[4], sE1[4], sO0[4], sO1[4];
        uint32_t pE[4], pO[4];

        qk_block(0, sE0, sE1);
        exppack(sE0, sE1, pE);
#pragma unroll
        for (int g = 1; g < 8; g++) {
            if (g & 1) {
                qk_block(g, sO0, sO1);
                pv_block(g - 1, pE);
                exppack(sO0, sO1, pO);
            } else {
                qk_block(g, sE0, sE1);
                pv_block(g - 1, pO);
                exppack(sE0, sE1, pE);
            }
        }
        pv_block(7, pO);
    }

    // epilogue: quad-reduce l, normalize, store ctx as single fp16
    l0 += __shfl_xor_sync(0xffffffffu, l0, 1);
    l0 += __shfl_xor_sync(0xffffffffu, l0, 2);
    l1 += __shfl_xor_sync(0xffffffffu, l1, 1);
    l1 += __shfl_xor_sync(0xffffffffu, l1, 2);
    const float inv0 = 1.f / l0;
    const float inv1 = 1.f / l1;
    const int row0 = q0 + wid * 16 + (lane >> 2);
    const int col0 = h * DH_ + 2 * (lane & 3);
    const size_t p0 = ((size_t)b * S_ + row0) * D_ + col0;
    const size_t p1 = p0 + 8 * D_;
#pragma unroll
    for (int nt = 0; nt < 8; nt++) {
        *reinterpret_cast<uint32_t*>(g_cf + p0 + nt * 8) =
            pack2h(o[nt][0] * inv0, o[nt][1] * inv0);
        *reinterpret_cast<uint32_t*>(g_cf + p1 + nt * 8) =
            pack2h(o[nt][2] * inv1, o[nt][3] * inv1);
    }
}

// ---------------------------------------------------------------------------
// Launch
// ---------------------------------------------------------------------------
extern "C" void kernel_launch(void* const* d_in, const int* in_sizes, int n_in,
                              void* d_out, int out_size)
{
    const float* x  = (const float*)d_in[0];
    const float* Wq = (const float*)d_in[1];
    const float* bq = (const float*)d_in[2];
    const float* Wk = (const float*)d_in[3];
    const float* bk = (const float*)d_in[4];
    const float* Wv = (const float*)d_in[5];
    const float* bv = (const float*)d_in[6];
    const float* Wo = (const float*)d_in[7];
    const float* bo = (const float*)d_in[8];
    const float* ls = (const float*)d_in[9];
    float* out = (float*)d_out;

    xconv_kernel<<<(M_ * D_) / 1024, 256>>>(x);
    wsplit_kernel<<<4 * (DD_ / 1024), 256>>>(Wq, Wk, Wv, Wo);

    cudaFuncSetAttribute(qkv_gemm, cudaFuncAttributeMaxDynamicSharedMemorySize, GEMM2_SMEM);
    cudaFuncSetAttribute(o_gemm,   cudaFuncAttributeMaxDynamicSharedMemorySize, GEMM2_SMEM);
    cudaFuncSetAttribute(attn_mma, cudaFuncAttributeMaxDynamicSharedMemorySize, ATTN_SMEM);

    qkv_gemm<<<dim3(18, M_ / 128), 256, GEMM2_SMEM>>>(bq, bk, bv, ls);

    attn_mma<<<dim3(S_ / 128, B_ * H_), 256, ATTN_SMEM>>>(ls);

    o_gemm<<<dim3(6, M_ / 128), 256, GEMM2_SMEM>>>(bo, out);
}

// round 16
// speedup vs baseline: 1.2327x; 1.2327x over previous
#include <cuda_runtime.h>
#include <cuda_fp16.h>
#include <math.h>
#include <cstdint>

#define B_  4
#define S_  2048
#define D_  768
#define H_  12
#define DH_ 64
#define M_  (B_*S_)          // 8192
#define NROWS_ (B_*H_*S_)    // 98304
#define QKVN_ (NROWS_*DH_)   // 6291456
#define DD_  (D_*D_)         // 589824
#define LOG2E_ 1.4426950408889634f

// Scratch (allocation-free: static __device__ globals)
__device__ __half g_xf[M_*D_];                     // x fp16
__device__ __half g_wf[4*DD_];                     // Wq,Wk,Wv,Wo fp16
__device__ __half g_qh[QKVN_];                     // q fp16 (prescaled, normalized)
__device__ __half g_kh[QKVN_];                     // k fp16 (normalized)
__device__ __half g_vh[QKVN_];                     // v fp16
__device__ __half g_cf[M_*D_];                     // ctx fp16

// ===========================================================================
// Helpers
// ===========================================================================
__device__ __forceinline__ uint32_t smem_u32(const void* p) {
    uint32_t r;
    asm("{ .reg .u64 t; cvta.to.shared.u64 t, %1; cvt.u32.u64 %0, t; }"
        : "=r"(r) : "l"(p));
    return r;
}
__device__ __forceinline__ void ldsm_x4(uint32_t* r, uint32_t addr) {
    asm volatile("ldmatrix.sync.aligned.m8n8.x4.shared.b16 {%0,%1,%2,%3}, [%4];"
                 : "=r"(r[0]), "=r"(r[1]), "=r"(r[2]), "=r"(r[3]) : "r"(addr));
}
__device__ __forceinline__ void ldsm_x4_t(uint32_t* r, uint32_t addr) {
    asm volatile("ldmatrix.sync.aligned.m8n8.x4.trans.shared.b16 {%0,%1,%2,%3}, [%4];"
                 : "=r"(r[0]), "=r"(r[1]), "=r"(r[2]), "=r"(r[3]) : "r"(addr));
}
// fp16 in, fp32 accum
__device__ __forceinline__ void mma16816h(float* d, const uint32_t* a,
                                          uint32_t b0, uint32_t b1) {
    asm volatile(
        "mma.sync.aligned.m16n8k16.row.col.f32.f16.f16.f32 "
        "{%0,%1,%2,%3}, {%4,%5,%6,%7}, {%8,%9}, {%0,%1,%2,%3};"
        : "+f"(d[0]), "+f"(d[1]), "+f"(d[2]), "+f"(d[3])
        : "r"(a[0]), "r"(a[1]), "r"(a[2]), "r"(a[3]), "r"(b0), "r"(b1));
}
// pack two fp32 -> fp16x2 (rn), element0 in low half
__device__ __forceinline__ uint32_t pack2h(float x0, float x1) {
    uint32_t d;
    asm("cvt.rn.f16x2.f32 %0, %1, %2;" : "=r"(d) : "f"(x1), "f"(x0));
    return d;
}
__device__ __forceinline__ float ex2(float x) {
    float y;
    asm("ex2.approx.f32 %0, %1;" : "=f"(y) : "f"(x));
    return y;
}
__device__ __forceinline__ void cp16(uint32_t dst, const void* src) {
    asm volatile("cp.async.cg.shared.global [%0], [%1], 16;" :: "r"(dst), "l"(src));
}
#define CP_COMMIT() asm volatile("cp.async.commit_group;" ::: "memory")
#define CP_WAIT(n)  asm volatile("cp.async.wait_group %0;" :: "n"(n) : "memory")

// ===========================================================================
// conversion kernels: fp32 -> fp16
// ===========================================================================
__global__ void __launch_bounds__(256)
xconv_kernel(const float* __restrict__ src)
{
    const int i = (blockIdx.x * 256 + threadIdx.x) * 4;
    float4 v = *reinterpret_cast<const float4*>(src + i);
    *reinterpret_cast<uint2*>(g_xf + i) =
        make_uint2(pack2h(v.x, v.y), pack2h(v.z, v.w));
}
__global__ void __launch_bounds__(256)
wconv_kernel(const float* __restrict__ Wq, const float* __restrict__ Wk,
             const float* __restrict__ Wv, const float* __restrict__ Wo)
{
    const int per = DD_ / 1024;                   // 576
    const int wsel = blockIdx.x / per;
    const int bx   = blockIdx.x % per;
    const float* src = (wsel == 0) ? Wq : (wsel == 1) ? Wk : (wsel == 2) ? Wv : Wo;
    const int i = (bx * 256 + threadIdx.x) * 4;
    float4 v = *reinterpret_cast<const float4*>(src + i);
    *reinterpret_cast<uint2*>(g_wf + (size_t)wsel * DD_ + i) =
        make_uint2(pack2h(v.x, v.y), pack2h(v.z, v.w));
}

// ===========================================================================
// fp16 1-combo GEMM mainloop: acc = A @ W^T, 128x128 tile, 3-stage ring.
// ===========================================================================
#define LDK_  40
#define GARR  10240
#define GEMM_SMEM (6 * GARR)        // 3 stages x {A, W} = 60KB

__device__ __forceinline__ void gemm_body(
    const __half* __restrict__ A, const __half* __restrict__ W,
    int m0, int n0, char* smem, float acc[4][4][4])
{
    const int tid    = threadIdx.x;
    const int lane   = tid & 31;
    const int wid    = tid >> 5;
    const int warp_m = wid & 1;
    const int warp_n = wid >> 1;
    const uint32_t sb = smem_u32(smem);

#pragma unroll
    for (int i = 0; i < 4; i++)
#pragma unroll
        for (int j = 0; j < 4; j++)
#pragma unroll
            for (int e = 0; e < 4; e++) acc[i][j][e] = 0.f;

    const int grow = tid >> 1;
    const int c16  = (tid & 1) * 2;
    const __half* s0 = A + (size_t)(m0 + grow) * D_;
    const __half* s1 = W + (size_t)(n0 + grow) * D_;

    auto issue = [&](int kc, int bsel) {
        const uint32_t dst = sb + bsel * 2 * GARR + grow * 80 + c16 * 16;
#pragma unroll
        for (int j = 0; j < 2; j++) {
            cp16(dst + j * 16,        s0 + kc + (c16 + j) * 8);
            cp16(dst + j * 16 + GARR, s1 + kc + (c16 + j) * 8);
        }
    };

    const int r_a = lane & 15, c_a = (lane >> 4) * 8;
    const int r_b = (lane & 7) | ((lane >> 4) << 3);
    const int c_b = ((lane >> 3) & 1) * 8;
    const uint32_t offA = ((warp_m * 64 + r_a) * LDK_ + c_a) * 2;
    const uint32_t offB = ((warp_n * 32 + r_b) * LDK_ + c_b) * 2;

    issue(0, 0);  CP_COMMIT();
    issue(32, 1); CP_COMMIT();

    const int NK = D_ / 32;   // 24
    for (int it = 0; it < NK; it++) {
        if (it + 1 < NK) { CP_WAIT(1); } else { CP_WAIT(0); }
        __syncthreads();
        if (it + 2 < NK) { issue((it + 2) * 32, (it + 2) % 3); CP_COMMIT(); }

        const uint32_t bA = sb + ((it % 3) * 2) * GARR;
        const uint32_t bW = bA + GARR;

#pragma unroll
        for (int ks = 0; ks < 2; ks++) {
            const uint32_t ko = ks * 32;
            uint32_t ah[4][4];
#pragma unroll
            for (int mt = 0; mt < 4; mt++)
                ldsm_x4(ah[mt], bA + offA + ko + mt * 16 * LDK_ * 2);
            uint32_t bh[8];
#pragma unroll
            for (int g = 0; g < 2; g++)
                ldsm_x4(&bh[g * 4], bW + offB + ko + g * 16 * LDK_ * 2);
#pragma unroll
            for (int mt = 0; mt < 4; mt++)
#pragma unroll
                for (int nt = 0; nt < 4; nt++)
                    mma16816h(acc[mt][nt], ah[mt], bh[nt * 2], bh[nt * 2 + 1]);
        }
    }
    __syncthreads();
}

// ===========================================================================
// fused QKV GEMM: grid.x = 18 (wsel = x/6: 0=q, 1=k, 2=v).
// q,k: + L2 norm (+ scale for q); v: bias only. fp16 head-split store.
// ===========================================================================
__global__ void __launch_bounds__(256, 2)
qkv_gemm(const float* __restrict__ bq, const float* __restrict__ bk,
         const float* __restrict__ bv, const float* __restrict__ ls)
{
    extern __shared__ char smem[];
    const int wsel = blockIdx.x / 6;
    const int n0   = (blockIdx.x % 6) * 128;
    const int m0   = blockIdx.y * 128;

    float acc[4][4][4];
    gemm_body(g_xf, g_wf + (size_t)wsel * DD_, m0, n0, smem, acc);

    const int tid  = threadIdx.x;
    const int lane = tid & 31;
    const int wid  = tid >> 5;
    const int warp_m = wid & 1, warp_n = wid >> 1;

    const float* bias = (wsel == 0) ? bq : (wsel == 1) ? bk : bv;
    __half* dst = (wsel == 0) ? g_qh : (wsel == 1) ? g_kh : g_vh;

    float2 bv2[4];
#pragma unroll
    for (int nt = 0; nt < 4; nt++)
        bv2[nt] = *reinterpret_cast<const float2*>(
            &bias[n0 + warp_n * 32 + nt * 8 + 2 * (lane & 3)]);
#pragma unroll
    for (int mt = 0; mt < 4; mt++)
#pragma unroll
        for (int nt = 0; nt < 4; nt++) {
            acc[mt][nt][0] += bv2[nt].x; acc[mt][nt][1] += bv2[nt].y;
            acc[mt][nt][2] += bv2[nt].x; acc[mt][nt][3] += bv2[nt].y;
        }

    float* sq = reinterpret_cast<float*>(smem);   // [128][4]
    if (wsel < 2) {
#pragma unroll
        for (int mt = 0; mt < 4; mt++)
#pragma unroll
            for (int half = 0; half < 2; half++) {
                const int r = warp_m * 64 + mt * 16 + (lane >> 2) + half * 8;
                float p = 0.f;
#pragma unroll
                for (int nt = 0; nt < 4; nt++) {
                    const float a = acc[mt][nt][half * 2], bvv = acc[mt][nt][half * 2 + 1];
                    p += a * a + bvv * bvv;
                }
                p += __shfl_xor_sync(0xffffffffu, p, 1);
                p += __shfl_xor_sync(0xffffffffu, p, 2);
                if ((lane & 3) == 0) sq[r * 4 + warp_n] = p;
            }
        __syncthreads();
    }

    float scl = 1.f;
    if (wsel == 0) {
        const int hh = 2 * (blockIdx.x % 6) + (warp_n >> 1);
        scl = __expf(fminf(ls[hh], 4.6051701859880914f)) * LOG2E_;
    }

#pragma unroll
    for (int mt = 0; mt < 4; mt++) {
#pragma unroll
        for (int half = 0; half < 2; half++) {
            const int r = warp_m * 64 + mt * 16 + (lane >> 2) + half * 8;
            float inv = 1.f;
            if (wsel < 2) {
                const float s2 = sq[r * 4 + (warp_n & 2)] + sq[r * 4 + (warp_n & 2) + 1];
                inv = scl / fmaxf(sqrtf(s2), 1e-12f);
            }
            const int m  = m0 + r;
            const int bb = m >> 11, ss = m & (S_ - 1);
#pragma unroll
            for (int nt = 0; nt < 4; nt++) {
                const int n  = n0 + warp_n * 32 + nt * 8 + 2 * (lane & 3);
                const int hh = n >> 6, dd = n & 63;
                const size_t idx = (((size_t)(bb * H_ + hh)) * S_ + ss) * DH_ + dd;
                *reinterpret_cast<uint32_t*>(&dst[idx]) =
                    pack2h(acc[mt][nt][half * 2] * inv, acc[mt][nt][half * 2 + 1] * inv);
            }
        }
    }
}

// output projection: ctx_f @ Wo^T + bo -> fp32 out
__global__ void __launch_bounds__(256, 2)
o_gemm(const float* __restrict__ bo, float* __restrict__ out)
{
    extern __shared__ char smem[];
    const int n0 = blockIdx.x * 128;
    const int m0 = blockIdx.y * 128;

    float acc[4][4][4];
    gemm_body(g_cf, g_wf + 3 * (size_t)DD_, m0, n0, smem, acc);

    const int lane = threadIdx.x & 31;
    const int wid  = threadIdx.x >> 5;
    const int warp_m = wid & 1, warp_n = wid >> 1;
#pragma unroll
    for (int mt = 0; mt < 4; mt++) {
#pragma unroll
        for (int nt = 0; nt < 4; nt++) {
            const int n = n0 + warp_n * 32 + nt * 8 + 2 * (lane & 3);
            const float2 bv2 = *reinterpret_cast<const float2*>(&bo[n]);
#pragma unroll
            for (int half = 0; half < 2; half++) {
                const int m = m0 + warp_m * 64 + mt * 16 + (lane >> 2) + half * 8;
                float2 o;
                o.x = acc[mt][nt][half * 2 + 0] + bv2.x;
                o.y = acc[mt][nt][half * 2 + 1] + bv2.y;
                *reinterpret_cast<float2*>(out + (size_t)m * D_ + n) = o;
            }
        }
    }
}

// ===========================================================================
// HMMA flash attention: 64-key tiles, 3-stage ring, fixed-max softmax,
// all single-fp16 tensor path (R14-proven config).
// ===========================================================================
#define ABUF   9216
#define ATTN_SMEM (6 * ABUF)       // 3 stages x {Kh, Vh}

__global__ void __launch_bounds__(256, 2)
attn_mma(const float* __restrict__ ls)
{
    extern __shared__ char sm[];
    const uint32_t sbase = smem_u32(sm);
    const int tid  = threadIdx.x;
    const int lane = tid & 31;
    const int wid  = tid >> 5;
    const int bh   = blockIdx.y;
    const int h    = bh % H_;
    const int b    = bh / H_;
    const int q0   = blockIdx.x * 128;
    const size_t base = (size_t)bh * S_ * DH_;
    const float Mfix = __expf(fminf(ls[h], 4.6051701859880914f)) * LOG2E_;

    // stage Q (fp16, 128x64) into smem, build A-fragments, release
    {
        const __half* gq = g_qh + base + (size_t)q0 * DH_;
#pragma unroll
        for (int i = 0; i < 4; i++) {
            const int idx = (i << 8) + tid;
            const int row = idx >> 3, c = idx & 7;
            const uint4 v = *reinterpret_cast<const uint4*>(gq + row * DH_ + c * 8);
            *reinterpret_cast<uint4*>(sm + row * 144 + c * 16) = v;
        }
    }
    __syncthreads();
    uint32_t qf[4][4];
    {
        const uint32_t qa = sbase + (wid * 16 + (lane & 15)) * 144 + (lane >> 4) * 16;
#pragma unroll
        for (int kt = 0; kt < 4; kt++)
            ldsm_x4(qf[kt], qa + kt * 32);
    }
    __syncthreads();

    float o[8][4];
#pragma unroll
    for (int nt = 0; nt < 8; nt++)
#pragma unroll
        for (int e = 0; e < 4; e++) o[nt][e] = 0.f;
    float l0 = 0.f, l1 = 0.f;

    const uint32_t lofs = (lane & 15) * 144 + (lane >> 4) * 16;

    const __half* gkh = g_kh + base;
    const __half* gvh = g_vh + base;

    auto issue = [&](int it, int bsel) {
        const int koff = it * 64 * DH_;
#pragma unroll
        for (int i = 0; i < 4; i++) {
            const int idx = (i << 8) + tid;
            const int arr = idx >> 9;
            const int row = (idx >> 3) & 63;
            const int c   = idx & 7;
            const __half* gp = (arr == 0 ? gkh : gvh) + koff + row * DH_ + c * 8;
            cp16(sbase + (bsel * 2 + arr) * ABUF + row * 144 + c * 16, gp);
        }
    };

    issue(0, 0); CP_COMMIT();
    issue(1, 1); CP_COMMIT();

    const int NIT = S_ / 64;   // 32
    for (int it = 0; it < NIT; it++) {
        if (it + 1 < NIT) { CP_WAIT(1); } else { CP_WAIT(0); }
        __syncthreads();
        if (it + 2 < NIT) { issue(it + 2, (it + 2) % 3); CP_COMMIT(); }

        const uint32_t Kh = sbase + ((it % 3) * 2) * ABUF;
        const uint32_t Vh = Kh + ABUF;

        auto qk_block = [&](int g, float* s0p, float* s1p) {
#pragma unroll
            for (int e = 0; e < 4; e++) { s0p[e] = -Mfix; s1p[e] = -Mfix; }
#pragma unroll
            for (int kt = 0; kt < 4; kt++) {
                uint32_t kf[4];
                ldsm_x4(kf, Kh + lofs + g * 16 * 144 + kt * 32);
                mma16816h(s0p, qf[kt], kf[0], kf[2]);
                mma16816h(s1p, qf[kt], kf[1], kf[3]);
            }
        };
        auto exppack = [&](float* s0p, float* s1p, uint32_t* ph) {
#pragma unroll
            for (int e = 0; e < 4; e++) { s0p[e] = ex2(s0p[e]); s1p[e] = ex2(s1p[e]); }
            l0 += s0p[0] + s0p[1] + s1p[0] + s1p[1];
            l1 += s0p[2] + s0p[3] + s1p[2] + s1p[3];
            ph[0] = pack2h(s0p[0], s0p[1]);
            ph[1] = pack2h(s0p[2], s0p[3]);
            ph[2] = pack2h(s1p[0], s1p[1]);
            ph[3] = pack2h(s1p[2], s1p[3]);
        };
        auto pv_block = [&](int g, const uint32_t* ph) {
#pragma unroll
            for (int og = 0; og < 4; og++) {
                uint32_t vf[4];
                ldsm_x4_t(vf, Vh + lofs + g * 16 * 144 + og * 32);
                mma16816h(o[2 * og],     ph, vf[0], vf[1]);
                mma16816h(o[2 * og + 1], ph, vf[2], vf[3]);
            }
        };

        float sA0[4], sA1[4], sB0[4], sB1[4];
        uint32_t pA[4], pB[4];

        qk_block(0, sA0, sA1);
        exppack(sA0, sA1, pA);

        qk_block(1, sB0, sB1);
        pv_block(0, pA);
        exppack(sB0, sB1, pB);

        qk_block(2, sA0, sA1);
        pv_block(1, pB);
        exppack(sA0, sA1, pA);

        qk_block(3, sB0, sB1);
        pv_block(2, pA);
        exppack(sB0, sB1, pB);

        pv_block(3, pB);
    }

    // epilogue: quad-reduce l, normalize, store ctx as single fp16
    l0 += __shfl_xor_sync(0xffffffffu, l0, 1);
    l0 += __shfl_xor_sync(0xffffffffu, l0, 2);
    l1 += __shfl_xor_sync(0xffffffffu, l1, 1);
    l1 += __shfl_xor_sync(0xffffffffu, l1, 2);
    const float inv0 = 1.f / l0;
    const float inv1 = 1.f / l1;
    const int row0 = q0 + wid * 16 + (lane >> 2);
    const int col0 = h * DH_ + 2 * (lane & 3);
    const size_t p0 = ((size_t)b * S_ + row0) * D_ + col0;
    const size_t p1 = p0 + 8 * D_;
#pragma unroll
    for (int nt = 0; nt < 8; nt++) {
        *reinterpret_cast<uint32_t*>(g_cf + p0 + nt * 8) =
            pack2h(o[nt][0] * inv0, o[nt][1] * inv0);
        *reinterpret_cast<uint32_t*>(g_cf + p1 + nt * 8) =
            pack2h(o[nt][2] * inv1, o[nt][3] * inv1);
    }
}

// ---------------------------------------------------------------------------
// Launch
// ---------------------------------------------------------------------------
extern "C" void kernel_launch(void* const* d_in, const int* in_sizes, int n_in,
                              void* d_out, int out_size)
{
    const float* x  = (const float*)d_in[0];
    const float* Wq = (const float*)d_in[1];
    const float* bq = (const float*)d_in[2];
    const float* Wk = (const float*)d_in[3];
    const float* bk = (const float*)d_in[4];
    const float* Wv = (const float*)d_in[5];
    const float* bv = (const float*)d_in[6];
    const float* Wo = (const float*)d_in[7];
    const float* bo = (const float*)d_in[8];
    const float* ls = (const float*)d_in[9];
    float* out = (float*)d_out;

    xconv_kernel<<<(M_ * D_) / 1024, 256>>>(x);
    wconv_kernel<<<4 * (DD_ / 1024), 256>>>(Wq, Wk, Wv, Wo);

    cudaFuncSetAttribute(qkv_gemm, cudaFuncAttributeMaxDynamicSharedMemorySize, GEMM_SMEM);
    cudaFuncSetAttribute(o_gemm,   cudaFuncAttributeMaxDynamicSharedMemorySize, GEMM_SMEM);
    cudaFuncSetAttribute(attn_mma, cudaFuncAttributeMaxDynamicSharedMemorySize, ATTN_SMEM);

    qkv_gemm<<<dim3(18, M_ / 128), 256, GEMM_SMEM>>>(bq, bk, bv, ls);

    attn_mma<<<dim3(S_ / 128, B_ * H_), 256, ATTN_SMEM>>>(ls);

    o_gemm<<<dim3(6, M_ / 128), 256, GEMM_SMEM>>>(bo, out);
}